// round 6
// baseline (speedup 1.0000x reference)
#include <cuda_runtime.h>
#include <math.h>
#include <stdint.h>

// ---------------- problem constants ----------------
#define BATCH   32
#define IMG     56
#define C       384
#define WS      7
#define SSH     3
#define NH      12
#define HD      32
#define NWIN    64
#define MROWS   (BATCH * IMG * IMG)       // 100352
#define TOKPI   (IMG * IMG)               // 3136
#define QKVC    (3 * C)                   // 1152
#define HIDDEN  (4 * C)                   // 1536

#define STAGES  3
#define BM      256
#define BN      128
#define APAD    36                        // A row stride: frag bank = 4g+t (injective)
#define BPAD    136                       // B row stride: frag bank = 8t+g (injective, 136%32==8)
#define A_STAGE (BM * APAD)               // 9216 floats
#define B_STAGE (32 * BPAD)               // 4352 floats
#define SMEM_BYTES (STAGES * (A_STAGE + B_STAGE) * 4)   // 162816

// ---------------- scratch ----------------
static __device__ float g_hw  [(size_t)MROWS * C];
static __device__ float g_qkv [(size_t)MROWS * QKVC];
static __device__ float g_att [(size_t)MROWS * C];
static __device__ float g_x2  [(size_t)MROWS * C];
static __device__ float g_fc1 [(size_t)MROWS * HIDDEN];

// ---------------- helpers ----------------
__device__ __forceinline__ void cp16(float* dst, const float* src) {
    uint32_t d = (uint32_t)__cvta_generic_to_shared(dst);
    asm volatile("cp.async.cg.shared.global [%0], [%1], 16;\n" :: "r"(d), "l"(src));
}
__device__ __forceinline__ void cp_commit() {
    asm volatile("cp.async.commit_group;\n" ::);
}
template<int N>
__device__ __forceinline__ void cp_wait() {
    asm volatile("cp.async.wait_group %0;\n" :: "n"(N));
}

__device__ __forceinline__ void mma_tf32(float c[4],
    uint32_t a0, uint32_t a1, uint32_t a2, uint32_t a3,
    uint32_t b0, uint32_t b1)
{
    asm volatile(
        "mma.sync.aligned.m16n8k8.row.col.f32.tf32.tf32.f32 "
        "{%0,%1,%2,%3},{%4,%5,%6,%7},{%8,%9},{%0,%1,%2,%3};"
        : "+f"(c[0]), "+f"(c[1]), "+f"(c[2]), "+f"(c[3])
        : "r"(a0), "r"(a1), "r"(a2), "r"(a3), "r"(b0), "r"(b1));
}

// ---------------- LayerNorm: warp-per-token (+ optional shift/window gather) ----------------
__global__ void __launch_bounds__(256) ln_kernel(
    const float* __restrict__ x, const float* __restrict__ gamma,
    const float* __restrict__ beta, float* __restrict__ out, int gather)
{
    int warp = threadIdx.x >> 5, lane = threadIdx.x & 31;
    int t = blockIdx.x * 8 + warp;
    if (t >= MROWS) return;
    int src;
    if (gather) {
        int b = t / TOKPI, rr = t % TOKPI;
        int wh = rr / 392; rr %= 392;
        int ww = rr / 49; int n = rr % 49;
        int i = n / 7, j = n % 7;
        int sr = (wh * 7 + i + SSH) % IMG;
        int sc = (ww * 7 + j + SSH) % IMG;
        src = b * TOKPI + sr * IMG + sc;
    } else {
        src = t;
    }
    const float* row = x + (size_t)src * C;
    float v[12];
    float s = 0.f, sq = 0.f;
    #pragma unroll
    for (int j = 0; j < 12; j++) {
        v[j] = row[lane + 32 * j];
        s += v[j];
        sq += v[j] * v[j];
    }
    #pragma unroll
    for (int o = 16; o > 0; o >>= 1) {
        s  += __shfl_xor_sync(0xffffffffu, s,  o);
        sq += __shfl_xor_sync(0xffffffffu, sq, o);
    }
    float mu = s * (1.0f / C);
    float var = sq * (1.0f / C) - mu * mu;
    float rs = rsqrtf(var + 1e-5f);
    float* orow = out + (size_t)t * C;
    #pragma unroll
    for (int j = 0; j < 12; j++) {
        int c = lane + 32 * j;
        orow[c] = (v[j] - mu) * rs * gamma[c] + beta[c];
    }
}

// ---------------- TF32 tensor-core GEMM: 256x128 CTA, 64x64 warp tile, 3-stage cp.async ----------------
#define EPI_NONE 0
#define EPI_GELU 1
#define EPI_PROJ 2
#define EPI_RES  3

template<int EPI>
__global__ void __launch_bounds__(256, 1) mma_gemm(
    const float* __restrict__ A, const float* __restrict__ W,
    const float* __restrict__ bias, float* __restrict__ out,
    const float* __restrict__ res, int NN, int KK)
{
    extern __shared__ float smem[];
    float* AsBase = smem;                       // [STAGES][BM][APAD]
    float* BsBase = smem + STAGES * A_STAGE;    // [STAGES][32][BPAD]

    int tid  = threadIdx.x;
    int lane = tid & 31, w = tid >> 5;
    int g = lane >> 2, t = lane & 3;
    int wm = (w >> 1) * 64;            // 0,64,128,192
    int wn = (w & 1) * 64;             // 0,64
    int brow = blockIdx.y * BM;
    int bcol = blockIdx.x * BN;

    float acc[4][8][4];
    #pragma unroll
    for (int mi = 0; mi < 4; mi++)
        #pragma unroll
        for (int ni = 0; ni < 8; ni++)
            #pragma unroll
            for (int q = 0; q < 4; q++) acc[mi][ni][q] = 0.f;

    // staging: A tile 256x32 = 2048 16B-chunks (8/thread); B tile 32x128 = 1024 (4/thread)
    int ar = tid >> 3, ak = (tid & 7) * 4;     // A rows ar+32i, i<8
    int bk = tid >> 5, bn = (tid & 31) * 4;    // B rows bk+8i,  i<4

    const float* Ag = A + (size_t)(brow + ar) * KK + ak;
    const float* Bg = W + (size_t)bk * NN + bcol + bn;

    const int kt = KK >> 5;

    // prologue
    #pragma unroll
    for (int s = 0; s < STAGES - 1; s++) {
        int k0 = s << 5;
        float* As = AsBase + s * A_STAGE;
        float* Bs = BsBase + s * B_STAGE;
        #pragma unroll
        for (int i = 0; i < 8; i++)
            cp16(As + (ar + 32 * i) * APAD + ak, Ag + (size_t)(32 * i) * KK + k0);
        #pragma unroll
        for (int i = 0; i < 4; i++)
            cp16(Bs + (bk + 8 * i) * BPAD + bn, Bg + (size_t)(k0 + 8 * i) * NN);
        cp_commit();
    }

    int s = 0;
    for (int it = 0; it < kt; it++) {
        cp_wait<STAGES - 2>();
        __syncthreads();

        int pf = it + STAGES - 1;
        if (pf < kt) {
            int ps = s + (STAGES - 1); if (ps >= STAGES) ps -= STAGES;
            int k0 = pf << 5;
            float* Asp = AsBase + ps * A_STAGE;
            float* Bsp = BsBase + ps * B_STAGE;
            #pragma unroll
            for (int i = 0; i < 8; i++)
                cp16(Asp + (ar + 32 * i) * APAD + ak, Ag + (size_t)(32 * i) * KK + k0);
            #pragma unroll
            for (int i = 0; i < 4; i++)
                cp16(Bsp + (bk + 8 * i) * BPAD + bn, Bg + (size_t)(k0 + 8 * i) * NN);
        }
        cp_commit();

        const float* As = AsBase + s * A_STAGE;
        const float* Bs = BsBase + s * B_STAGE;

        #pragma unroll
        for (int ks = 0; ks < 4; ks++) {
            int kb = ks * 8;
            uint32_t af[4][4], bf[8][2];
            #pragma unroll
            for (int mi = 0; mi < 4; mi++) {
                int m0 = wm + mi * 16 + g;
                af[mi][0] = __float_as_uint(As[(m0)     * APAD + kb + t]);
                af[mi][1] = __float_as_uint(As[(m0 + 8) * APAD + kb + t]);
                af[mi][2] = __float_as_uint(As[(m0)     * APAD + kb + t + 4]);
                af[mi][3] = __float_as_uint(As[(m0 + 8) * APAD + kb + t + 4]);
            }
            #pragma unroll
            for (int ni = 0; ni < 8; ni++) {
                int n0 = wn + ni * 8 + g;
                bf[ni][0] = __float_as_uint(Bs[(kb + t)     * BPAD + n0]);
                bf[ni][1] = __float_as_uint(Bs[(kb + t + 4) * BPAD + n0]);
            }
            #pragma unroll
            for (int mi = 0; mi < 4; mi++)
                #pragma unroll
                for (int ni = 0; ni < 8; ni++)
                    mma_tf32(acc[mi][ni], af[mi][0], af[mi][1], af[mi][2], af[mi][3],
                             bf[ni][0], bf[ni][1]);
        }
        if (++s == STAGES) s = 0;
    }

    // epilogue
    #pragma unroll
    for (int mi = 0; mi < 4; mi++) {
        int r0 = brow + wm + mi * 16 + g;
        int r1 = r0 + 8;
        size_t o0, o1;
        if (EPI == EPI_PROJ) {
            #pragma unroll
            for (int h = 0; h < 2; h++) {
                int r = h ? r1 : r0;
                int b = r / TOKPI, rr = r % TOKPI;
                int wh = rr / 392; rr %= 392;
                int ww = rr / 49; int n = rr % 49;
                int ii = n / 7, jj = n % 7;
                int sr = (wh * 7 + ii + SSH) % IMG;
                int sc = (ww * 7 + jj + SSH) % IMG;
                size_t v = (size_t)(b * TOKPI + sr * IMG + sc);
                if (h) o1 = v; else o0 = v;
            }
        } else {
            o0 = (size_t)r0; o1 = (size_t)r1;
        }
        #pragma unroll
        for (int ni = 0; ni < 8; ni++) {
            int c = bcol + wn + ni * 8 + 2 * t;
            float blo = bias[c], bhi = bias[c + 1];
            float v00 = acc[mi][ni][0] + blo;
            float v01 = acc[mi][ni][1] + bhi;
            float v10 = acc[mi][ni][2] + blo;
            float v11 = acc[mi][ni][3] + bhi;
            if (EPI == EPI_GELU) {
                v00 = 0.5f * v00 * (1.f + erff(v00 * 0.70710678118654752f));
                v01 = 0.5f * v01 * (1.f + erff(v01 * 0.70710678118654752f));
                v10 = 0.5f * v10 * (1.f + erff(v10 * 0.70710678118654752f));
                v11 = 0.5f * v11 * (1.f + erff(v11 * 0.70710678118654752f));
            }
            if (EPI == EPI_PROJ || EPI == EPI_RES) {
                v00 += res[o0 * NN + c];
                v01 += res[o0 * NN + c + 1];
                v10 += res[o1 * NN + c];
                v11 += res[o1 * NN + c + 1];
            }
            float2 lo = { v00, v01 };
            float2 hi = { v10, v11 };
            *(float2*)&out[o0 * NN + c] = lo;
            *(float2*)&out[o1 * NN + c] = hi;
        }
    }
}

// ---------------- windowed attention ----------------
__device__ __forceinline__ int regid(int r) { return r < (IMG - WS) ? 0 : (r < (IMG - SSH) ? 1 : 2); }

__global__ void __launch_bounds__(128) attn_kernel(
    const float* __restrict__ qkv, const float* __restrict__ bias_table,
    float* __restrict__ o)
{
    int h  = blockIdx.x;
    int w  = blockIdx.y;
    int nw = w & 63;
    int wh = nw >> 3, ww = nw & 7;
    int tid = threadIdx.x;

    __shared__ float sq[49][33], sk[49][33], sv[49][32];
    __shared__ float ss[49][50];
    __shared__ float rsum[49];

    const float scale = 0.1767766952966369f;
    size_t base = (size_t)w * 49 * QKVC + h * HD;
    for (int idx = tid; idx < 49 * 32; idx += 128) {
        int n = idx >> 5, d = idx & 31;
        size_t rb = base + (size_t)n * QKVC + d;
        sq[n][d] = qkv[rb] * scale;
        sk[n][d] = qkv[rb + C];
        sv[n][d] = qkv[rb + 2 * C];
    }
    __syncthreads();

    for (int idx = tid; idx < 49 * 49; idx += 128) {
        int n = idx / 49, m = idx % 49;
        float dot = 0.f;
        #pragma unroll
        for (int d = 0; d < 32; d++) dot = fmaf(sq[n][d], sk[m][d], dot);
        int i1 = n / 7, j1 = n % 7, i2 = m / 7, j2 = m % 7;
        int ridx = (i1 - i2 + 6) * 13 + (j1 - j2 + 6);
        dot += bias_table[ridx * NH + h];
        int rn = regid(wh * 7 + i1) * 3 + regid(ww * 7 + j1);
        int rm = regid(wh * 7 + i2) * 3 + regid(ww * 7 + j2);
        if (rn != rm) dot -= 100.f;
        ss[n][m] = dot;
    }
    __syncthreads();

    if (tid < 49) {
        float mx = -1e30f;
        #pragma unroll 7
        for (int m = 0; m < 49; m++) mx = fmaxf(mx, ss[tid][m]);
        float sum = 0.f;
        #pragma unroll 7
        for (int m = 0; m < 49; m++) {
            float e = __expf(ss[tid][m] - mx);
            ss[tid][m] = e;
            sum += e;
        }
        rsum[tid] = 1.f / sum;
    }
    __syncthreads();

    for (int idx = tid; idx < 49 * 32; idx += 128) {
        int n = idx >> 5, d = idx & 31;
        float acc = 0.f;
        #pragma unroll 7
        for (int m = 0; m < 49; m++) acc = fmaf(ss[n][m], sv[m][d], acc);
        acc *= rsum[n];
        o[((size_t)w * 49 + n) * C + h * HD + d] = acc;
    }
}

// ---------------- launcher ----------------
extern "C" void kernel_launch(void* const* d_in, const int* in_sizes, int n_in,
                              void* d_out, int out_size)
{
    const float* x      = (const float*)d_in[0];
    const float* n1g    = (const float*)d_in[1];
    const float* n1b    = (const float*)d_in[2];
    const float* qkv_w  = (const float*)d_in[3];
    const float* qkv_b  = (const float*)d_in[4];
    const float* btab   = (const float*)d_in[5];
    const float* proj_w = (const float*)d_in[6];
    const float* proj_b = (const float*)d_in[7];
    const float* n2g    = (const float*)d_in[8];
    const float* n2b    = (const float*)d_in[9];
    const float* fc1_w  = (const float*)d_in[10];
    const float* fc1_b  = (const float*)d_in[11];
    const float* fc2_w  = (const float*)d_in[12];
    const float* fc2_b  = (const float*)d_in[13];
    float* out = (float*)d_out;

    float *hw, *qkv, *att, *x2, *fc1;
    cudaGetSymbolAddress((void**)&hw,  g_hw);
    cudaGetSymbolAddress((void**)&qkv, g_qkv);
    cudaGetSymbolAddress((void**)&att, g_att);
    cudaGetSymbolAddress((void**)&x2,  g_x2);
    cudaGetSymbolAddress((void**)&fc1, g_fc1);

    cudaFuncSetAttribute(mma_gemm<EPI_NONE>, cudaFuncAttributeMaxDynamicSharedMemorySize, SMEM_BYTES);
    cudaFuncSetAttribute(mma_gemm<EPI_GELU>, cudaFuncAttributeMaxDynamicSharedMemorySize, SMEM_BYTES);
    cudaFuncSetAttribute(mma_gemm<EPI_PROJ>, cudaFuncAttributeMaxDynamicSharedMemorySize, SMEM_BYTES);
    cudaFuncSetAttribute(mma_gemm<EPI_RES>,  cudaFuncAttributeMaxDynamicSharedMemorySize, SMEM_BYTES);

    const int gy = MROWS / BM;  // 392

    // 1. LN1 + shift + window partition
    ln_kernel<<<MROWS / 8, 256>>>(x, n1g, n1b, hw, 1);

    // 2. QKV GEMM
    mma_gemm<EPI_NONE><<<dim3(QKVC / BN, gy), 256, SMEM_BYTES>>>(hw, qkv_w, qkv_b, qkv, nullptr, QKVC, C);

    // 3. windowed attention
    attn_kernel<<<dim3(NH, BATCH * NWIN), 128>>>(qkv, btab, att);

    // 4. proj GEMM + scatter + residual
    mma_gemm<EPI_PROJ><<<dim3(C / BN, gy), 256, SMEM_BYTES>>>(att, proj_w, proj_b, x2, x, C, C);

    // 5. LN2
    ln_kernel<<<MROWS / 8, 256>>>(x2, n2g, n2b, hw, 0);

    // 6. FC1 + GELU
    mma_gemm<EPI_GELU><<<dim3(HIDDEN / BN, gy), 256, SMEM_BYTES>>>(hw, fc1_w, fc1_b, fc1, nullptr, HIDDEN, C);

    // 7. FC2 + residual
    mma_gemm<EPI_RES><<<dim3(C / BN, gy), 256, SMEM_BYTES>>>(fc1, fc2_w, fc2_b, out, x2, C, HIDDEN);
}